// round 4
// baseline (speedup 1.0000x reference)
#include <cuda_runtime.h>

#define N_NODES 100000
#define N_EDGES 1600000
#define C 128
#define NG 128
#define LSLOPE 0.01f

// ---------------- scratch (device globals: no allocation allowed) ----------
__device__ __align__(16) float g_B1[(size_t)N_NODES * C];   // GEMM output H
__device__ __align__(16) float g_B2[(size_t)N_NODES * C];   // AGG / layer input
__device__ float g_deg[N_NODES];
__device__ float g_dinv[N_NODES];
__device__ __align__(16) float g_sums[NG * C];
__device__ float g_cnts[NG];

__device__ __forceinline__ float lrelu(float v) { return v > 0.f ? v : LSLOPE * v; }

// ---------------- prep: zero accumulators ----------------------------------
__global__ void zero_prep_kernel() {
    int i = blockIdx.x * blockDim.x + threadIdx.x;
    if (i < N_NODES) g_deg[i] = 0.f;
    if (i < NG * C)  g_sums[i] = 0.f;
    if (i < NG)      g_cnts[i] = 0.f;
}

// ---------------- degree + dinv ---------------------------------------------
__global__ void deg_kernel(const int* __restrict__ ei) {
    int e = blockIdx.x * blockDim.x + threadIdx.x;
    if (e < N_EDGES) {
        unsigned d = (unsigned)ei[N_EDGES + e];
        if (d < N_NODES) atomicAdd(&g_deg[d], 1.0f);
    }
}

__global__ void dinv_kernel() {
    int i = blockIdx.x * blockDim.x + threadIdx.x;
    if (i < N_NODES) g_dinv[i] = rsqrtf(g_deg[i] + 1.0f);
}

// ---------------- fused GEMM: H = act(X) @ W ; AGG = H * dinv^2 ------------
// TRANSFORM=false: X = external x (layer 1), no input activation.
// TRANSFORM=true:  X = g_B2, input element v -> lrelu(v + bin[k]) (layer 2).
// Writes H -> g_B1, AGG -> g_B2. Block = 32 rows x 128 cols, 256 threads.
template <bool TRANSFORM>
__global__ __launch_bounds__(256)
void gemm_kernel(const float* __restrict__ Xext, const float* __restrict__ W,
                 const float* __restrict__ bin)
{
    __shared__ float  Xs[32][33];
    __shared__ float4 Ws4[32][32];   // [kk][col/4]

    const float* __restrict__ X = TRANSFORM ? (const float*)g_B2 : Xext;

    int tid  = threadIdx.x;
    int row0 = blockIdx.x * 32;
    int tx   = tid & 31;     // col group (cols tx*4 .. tx*4+3)
    int ty   = tid >> 5;     // row group (rows ty*4 .. ty*4+3)

    float acc[4][4];
#pragma unroll
    for (int i = 0; i < 4; i++)
#pragma unroll
        for (int j = 0; j < 4; j++) acc[i][j] = 0.f;

    for (int kt = 0; kt < 4; ++kt) {
        {
            int r = tid >> 3;
            int c = (tid & 7) * 4;
            int kcol = kt * 32 + c;
            float4 v = *(const float4*)(X + (size_t)(row0 + r) * C + kcol);
            if (TRANSFORM) {
                v.x = lrelu(v.x + bin[kcol + 0]);
                v.y = lrelu(v.y + bin[kcol + 1]);
                v.z = lrelu(v.z + bin[kcol + 2]);
                v.w = lrelu(v.w + bin[kcol + 3]);
            }
            Xs[r][c + 0] = v.x; Xs[r][c + 1] = v.y;
            Xs[r][c + 2] = v.z; Xs[r][c + 3] = v.w;
        }
#pragma unroll
        for (int i = 0; i < 4; i++) {
            int idx = tid + i * 256;
            int kk  = idx >> 5;
            int c4  = idx & 31;
            Ws4[kk][c4] = *(const float4*)(W + (size_t)(kt * 32 + kk) * C + c4 * 4);
        }
        __syncthreads();

#pragma unroll
        for (int kk = 0; kk < 32; ++kk) {
            float x0 = Xs[ty * 4 + 0][kk];
            float x1 = Xs[ty * 4 + 1][kk];
            float x2 = Xs[ty * 4 + 2][kk];
            float x3 = Xs[ty * 4 + 3][kk];
            float4 w = Ws4[kk][tx];
            acc[0][0] += x0 * w.x; acc[0][1] += x0 * w.y; acc[0][2] += x0 * w.z; acc[0][3] += x0 * w.w;
            acc[1][0] += x1 * w.x; acc[1][1] += x1 * w.y; acc[1][2] += x1 * w.z; acc[1][3] += x1 * w.w;
            acc[2][0] += x2 * w.x; acc[2][1] += x2 * w.y; acc[2][2] += x2 * w.z; acc[2][3] += x2 * w.w;
            acc[3][0] += x3 * w.x; acc[3][1] += x3 * w.y; acc[3][2] += x3 * w.z; acc[3][3] += x3 * w.w;
        }
        __syncthreads();
    }

#pragma unroll
    for (int i = 0; i < 4; i++) {
        int r = row0 + ty * 4 + i;
        float d  = g_dinv[r];
        float d2 = d * d;
        float4 h = make_float4(acc[i][0], acc[i][1], acc[i][2], acc[i][3]);
        *(float4*)(g_B1 + (size_t)r * C + tx * 4) = h;
        float4 a = make_float4(h.x * d2, h.y * d2, h.z * d2, h.w * d2);
        *(float4*)(g_B2 + (size_t)r * C + tx * 4) = a;
    }
}

// ---------------- edge scatter: AGG[dst] += H[src] * dinv[src]*dinv[dst] ---
__global__ __launch_bounds__(256)
void scatter_kernel(const int* __restrict__ ei)
{
    int warp = (blockIdx.x * blockDim.x + threadIdx.x) >> 5;
    int lane = threadIdx.x & 31;
    if (warp >= N_EDGES) return;
    unsigned s = (unsigned)ei[warp];
    unsigned d = (unsigned)ei[N_EDGES + warp];
    if (s >= N_NODES || d >= N_NODES) return;
    float norm = g_dinv[s] * g_dinv[d];
    float4 v = *(const float4*)(g_B1 + (size_t)s * C + lane * 4);
    float* p = g_B2 + (size_t)d * C + lane * 4;
    atomicAdd(p + 0, v.x * norm);
    atomicAdd(p + 1, v.y * norm);
    atomicAdd(p + 2, v.z * norm);
    atomicAdd(p + 3, v.w * norm);
}

// ---------------- pool: sums[g] += lrelu(AGG + b2); cnts[g] += 1 ------------
__global__ __launch_bounds__(256)
void pool_kernel(const int* __restrict__ batch, const float* __restrict__ b2)
{
    int node = (blockIdx.x * blockDim.x + threadIdx.x) >> 5;
    int lane = threadIdx.x & 31;
    if (node >= N_NODES) return;
    unsigned g = (unsigned)batch[node];
    if (g >= NG) return;
    float4 v = *(const float4*)(g_B2 + (size_t)node * C + lane * 4);
    float4 b = *(const float4*)(b2 + lane * 4);
    v.x = lrelu(v.x + b.x); v.y = lrelu(v.y + b.y);
    v.z = lrelu(v.z + b.z); v.w = lrelu(v.w + b.w);
    float* p = g_sums + g * C + lane * 4;
    atomicAdd(p + 0, v.x);
    atomicAdd(p + 1, v.y);
    atomicAdd(p + 2, v.z);
    atomicAdd(p + 3, v.w);
    if (lane == 0) atomicAdd(&g_cnts[g], 1.0f);
}

// ---------------- MLP head ---------------------------------------------------
__global__ __launch_bounds__(128)
void head_kernel(const float* __restrict__ W3, const float* __restrict__ b3,
                 const float* __restrict__ W4, const float* __restrict__ b4,
                 const float* __restrict__ W5, const float* __restrict__ b5,
                 float* __restrict__ out)
{
    int g = blockIdx.x;
    int t = threadIdx.x;
    __shared__ float gv[128], t1[64], t2[64];

    float inv = 1.0f / fmaxf(g_cnts[g], 1.0f);
    gv[t] = g_sums[g * C + t] * inv;
    __syncthreads();

    if (t < 64) {
        float s = b3[t];
#pragma unroll 8
        for (int k = 0; k < 128; k++) s += gv[k] * W3[k * 64 + t];
        t1[t] = lrelu(s);
    }
    __syncthreads();
    if (t < 64) {
        float s = b4[t];
#pragma unroll 8
        for (int k = 0; k < 64; k++) s += t1[k] * W4[k * 64 + t];
        t2[t] = lrelu(s);
    }
    __syncthreads();
    if (t < 10) {
        float s = b5[t];
#pragma unroll 8
        for (int k = 0; k < 64; k++) s += t2[k] * W5[k * 10 + t];
        out[g * 10 + t] = s;
    }
}

// ---------------- launch ----------------------------------------------------
// Inputs resolved by ELEMENT COUNT (ordering-agnostic). edge_index/batch are
// int32 (JAX x64 disabled downcasts int64 -> int32).
extern "C" void kernel_launch(void* const* d_in, const int* in_sizes, int n_in,
                              void* d_out, int out_size)
{
    const float* x = nullptr;
    const int* ei = nullptr;
    const int* batch = nullptr;
    const float *W1 = nullptr, *b1 = nullptr, *W2 = nullptr, *b2 = nullptr;
    const float *W3 = nullptr, *b3 = nullptr, *W4 = nullptr, *b4 = nullptr;
    const float *W5 = nullptr, *b5 = nullptr;

    for (int i = 0; i < n_in; i++) {
        const void* p = d_in[i];
        switch (in_sizes[i]) {
            case 12800000: x = (const float*)p; break;                       // 100000*128
            case 3200000:  ei = (const int*)p; break;                        // 2*1600000
            case 100000:   batch = (const int*)p; break;
            case 16384:    if (!W1) W1 = (const float*)p; else W2 = (const float*)p; break;
            case 8192:     W3 = (const float*)p; break;
            case 4096:     W4 = (const float*)p; break;
            case 640:      W5 = (const float*)p; break;
            case 128:      if (!b1) b1 = (const float*)p; else b2 = (const float*)p; break;
            case 64:       if (!b3) b3 = (const float*)p; else b4 = (const float*)p; break;
            case 10:       b5 = (const float*)p; break;
            default: break;
        }
    }
    float* out = (float*)d_out;
    (void)out_size;

    zero_prep_kernel<<<(N_NODES + 255) / 256, 256>>>();
    deg_kernel<<<(N_EDGES + 255) / 256, 256>>>(ei);
    dinv_kernel<<<(N_NODES + 255) / 256, 256>>>();

    // layer 1: H = x@W1 -> B1 ; AGG = H*dinv^2 -> B2 ; scatter edges
    gemm_kernel<false><<<N_NODES / 32, 256>>>(x, W1, nullptr);
    scatter_kernel<<<(N_EDGES * 32) / 256, 256>>>(ei);

    // layer 2: input lrelu(B2 + b1); H -> B1 ; AGG -> B2 ; scatter
    gemm_kernel<true><<<N_NODES / 32, 256>>>(nullptr, W2, b1);
    scatter_kernel<<<(N_EDGES * 32) / 256, 256>>>(ei);

    // pool lrelu(B2 + b2) per graph
    pool_kernel<<<(N_NODES * 32 + 255) / 256, 256>>>(batch, b2);

    // MLP head
    head_kernel<<<NG, 128>>>(W3, b3, W4, b4, W5, b5, out);
}

// round 5
// speedup vs baseline: 1.5422x; 1.5422x over previous
#include <cuda_runtime.h>

#define N_NODES 100000
#define N_EDGES 1600000
#define C 128
#define NG 128
#define LSLOPE 0.01f

// ---------------- scratch (device globals: no allocation allowed) ----------
__device__ __align__(16) float g_B1[(size_t)N_NODES * C];   // GEMM output H
__device__ __align__(16) float g_B2[(size_t)N_NODES * C];   // AGG / layer input
__device__ int   g_deg_i[N_NODES];
__device__ float g_dinv[N_NODES];
__device__ int   g_off[N_NODES + 1];       // CSR offsets (by dst)
__device__ int   g_cursor[N_NODES];        // fill cursors
__device__ int   g_esrc[N_EDGES];          // src per CSR slot
__device__ float g_enorm[N_EDGES];         // dinv[s]*dinv[d] per CSR slot
__device__ __align__(16) float g_sums[NG * C];
__device__ float g_cnts[NG];

__device__ __forceinline__ float lrelu(float v) { return v > 0.f ? v : LSLOPE * v; }

// ---------------- prep: zero accumulators ----------------------------------
__global__ void zero_prep_kernel() {
    int i = blockIdx.x * blockDim.x + threadIdx.x;
    if (i < N_NODES) g_deg_i[i] = 0;
    if (i < NG * C)  g_sums[i] = 0.f;
    if (i < NG)      g_cnts[i] = 0.f;
}

// ---------------- degree histogram (int) ------------------------------------
__global__ void deg_kernel(const int* __restrict__ ei) {
    int e = blockIdx.x * blockDim.x + threadIdx.x;
    if (e < N_EDGES) {
        unsigned d = (unsigned)ei[N_EDGES + e];
        if (d < N_NODES) atomicAdd(&g_deg_i[d], 1);
    }
}

// ---------------- single-block scan: offsets, cursors, dinv -----------------
__global__ __launch_bounds__(1024)
void scan_kernel() {
    __shared__ int part[1024];
    const int CHUNK = (N_NODES + 1023) / 1024;   // 98
    int t = threadIdx.x;
    int start = t * CHUNK;
    int end = min(start + CHUNK, N_NODES);

    int s = 0;
    for (int i = start; i < end; i++) s += g_deg_i[i];
    part[t] = s;
    __syncthreads();

    // Hillis-Steele inclusive scan over the 1024 partials
    for (int off = 1; off < 1024; off <<= 1) {
        int v = (t >= off) ? part[t - off] : 0;
        __syncthreads();
        part[t] += v;
        __syncthreads();
    }

    int running = part[t] - s;   // exclusive base for this chunk
    for (int i = start; i < end; i++) {
        g_off[i] = running;
        g_cursor[i] = running;
        int d = g_deg_i[i];
        running += d;
        g_dinv[i] = rsqrtf((float)d + 1.0f);
    }
    if (t == 1023) g_off[N_NODES] = running;
}

// ---------------- CSR fill: permute edges by dst -----------------------------
__global__ void fill_kernel(const int* __restrict__ ei) {
    int e = blockIdx.x * blockDim.x + threadIdx.x;
    if (e >= N_EDGES) return;
    unsigned s = (unsigned)ei[e];
    unsigned d = (unsigned)ei[N_EDGES + e];
    if (s >= N_NODES || d >= N_NODES) return;
    int pos = atomicAdd(&g_cursor[d], 1);
    g_esrc[pos]  = (int)s;
    g_enorm[pos] = g_dinv[s] * g_dinv[d];
}

// ---------------- fused GEMM: H = act(X) @ W ; AGG = H * dinv^2 ------------
template <bool TRANSFORM>
__global__ __launch_bounds__(256)
void gemm_kernel(const float* __restrict__ Xext, const float* __restrict__ W,
                 const float* __restrict__ bin)
{
    __shared__ float  Xs[32][33];
    __shared__ float4 Ws4[32][32];   // [kk][col/4]

    const float* __restrict__ X = TRANSFORM ? (const float*)g_B2 : Xext;

    int tid  = threadIdx.x;
    int row0 = blockIdx.x * 32;
    int tx   = tid & 31;
    int ty   = tid >> 5;

    float acc[4][4];
#pragma unroll
    for (int i = 0; i < 4; i++)
#pragma unroll
        for (int j = 0; j < 4; j++) acc[i][j] = 0.f;

    for (int kt = 0; kt < 4; ++kt) {
        {
            int r = tid >> 3;
            int c = (tid & 7) * 4;
            int kcol = kt * 32 + c;
            float4 v = *(const float4*)(X + (size_t)(row0 + r) * C + kcol);
            if (TRANSFORM) {
                v.x = lrelu(v.x + bin[kcol + 0]);
                v.y = lrelu(v.y + bin[kcol + 1]);
                v.z = lrelu(v.z + bin[kcol + 2]);
                v.w = lrelu(v.w + bin[kcol + 3]);
            }
            Xs[r][c + 0] = v.x; Xs[r][c + 1] = v.y;
            Xs[r][c + 2] = v.z; Xs[r][c + 3] = v.w;
        }
#pragma unroll
        for (int i = 0; i < 4; i++) {
            int idx = tid + i * 256;
            int kk  = idx >> 5;
            int c4  = idx & 31;
            Ws4[kk][c4] = *(const float4*)(W + (size_t)(kt * 32 + kk) * C + c4 * 4);
        }
        __syncthreads();

#pragma unroll
        for (int kk = 0; kk < 32; ++kk) {
            float x0 = Xs[ty * 4 + 0][kk];
            float x1 = Xs[ty * 4 + 1][kk];
            float x2 = Xs[ty * 4 + 2][kk];
            float x3 = Xs[ty * 4 + 3][kk];
            float4 w = Ws4[kk][tx];
            acc[0][0] += x0 * w.x; acc[0][1] += x0 * w.y; acc[0][2] += x0 * w.z; acc[0][3] += x0 * w.w;
            acc[1][0] += x1 * w.x; acc[1][1] += x1 * w.y; acc[1][2] += x1 * w.z; acc[1][3] += x1 * w.w;
            acc[2][0] += x2 * w.x; acc[2][1] += x2 * w.y; acc[2][2] += x2 * w.z; acc[2][3] += x2 * w.w;
            acc[3][0] += x3 * w.x; acc[3][1] += x3 * w.y; acc[3][2] += x3 * w.z; acc[3][3] += x3 * w.w;
        }
        __syncthreads();
    }

#pragma unroll
    for (int i = 0; i < 4; i++) {
        int r = row0 + ty * 4 + i;
        float d  = g_dinv[r];
        float d2 = d * d;
        float4 h = make_float4(acc[i][0], acc[i][1], acc[i][2], acc[i][3]);
        *(float4*)(g_B1 + (size_t)r * C + tx * 4) = h;
        float4 a = make_float4(h.x * d2, h.y * d2, h.z * d2, h.w * d2);
        *(float4*)(g_B2 + (size_t)r * C + tx * 4) = a;
    }
}

// ---------------- aggregation: warp per dst node, register accumulation -----
__global__ __launch_bounds__(256)
void agg_kernel()
{
    int node = (blockIdx.x * blockDim.x + threadIdx.x) >> 5;
    int lane = threadIdx.x & 31;
    if (node >= N_NODES) return;

    int beg = g_off[node];
    int end = g_off[node + 1];

    float4 a0 = make_float4(0.f, 0.f, 0.f, 0.f);
    float4 a1 = make_float4(0.f, 0.f, 0.f, 0.f);

    int i = beg;
    // 2-deep unroll for MLP on the gathers
    for (; i + 2 <= end; i += 2) {
        int   s0 = g_esrc[i];
        int   s1 = g_esrc[i + 1];
        float n0 = g_enorm[i];
        float n1 = g_enorm[i + 1];
        float4 v0 = *(const float4*)(g_B1 + (size_t)s0 * C + lane * 4);
        float4 v1 = *(const float4*)(g_B1 + (size_t)s1 * C + lane * 4);
        a0.x += v0.x * n0; a0.y += v0.y * n0; a0.z += v0.z * n0; a0.w += v0.w * n0;
        a1.x += v1.x * n1; a1.y += v1.y * n1; a1.z += v1.z * n1; a1.w += v1.w * n1;
    }
    if (i < end) {
        int   s0 = g_esrc[i];
        float n0 = g_enorm[i];
        float4 v0 = *(const float4*)(g_B1 + (size_t)s0 * C + lane * 4);
        a0.x += v0.x * n0; a0.y += v0.y * n0; a0.z += v0.z * n0; a0.w += v0.w * n0;
    }

    float* p = g_B2 + (size_t)node * C + lane * 4;   // holds self-loop term
    float4 cur = *(const float4*)p;
    cur.x += a0.x + a1.x;
    cur.y += a0.y + a1.y;
    cur.z += a0.z + a1.z;
    cur.w += a0.w + a1.w;
    *(float4*)p = cur;
}

// ---------------- pool: sums[g] += lrelu(AGG + b2); cnts[g] += 1 ------------
__global__ __launch_bounds__(256)
void pool_kernel(const int* __restrict__ batch, const float* __restrict__ b2)
{
    int node = (blockIdx.x * blockDim.x + threadIdx.x) >> 5;
    int lane = threadIdx.x & 31;
    if (node >= N_NODES) return;
    unsigned g = (unsigned)batch[node];
    if (g >= NG) return;
    float4 v = *(const float4*)(g_B2 + (size_t)node * C + lane * 4);
    float4 b = *(const float4*)(b2 + lane * 4);
    v.x = lrelu(v.x + b.x); v.y = lrelu(v.y + b.y);
    v.z = lrelu(v.z + b.z); v.w = lrelu(v.w + b.w);
    float* p = g_sums + g * C + lane * 4;
    atomicAdd(p + 0, v.x);
    atomicAdd(p + 1, v.y);
    atomicAdd(p + 2, v.z);
    atomicAdd(p + 3, v.w);
    if (lane == 0) atomicAdd(&g_cnts[g], 1.0f);
}

// ---------------- MLP head ---------------------------------------------------
__global__ __launch_bounds__(128)
void head_kernel(const float* __restrict__ W3, const float* __restrict__ b3,
                 const float* __restrict__ W4, const float* __restrict__ b4,
                 const float* __restrict__ W5, const float* __restrict__ b5,
                 float* __restrict__ out)
{
    int g = blockIdx.x;
    int t = threadIdx.x;
    __shared__ float gv[128], t1[64], t2[64];

    float inv = 1.0f / fmaxf(g_cnts[g], 1.0f);
    gv[t] = g_sums[g * C + t] * inv;
    __syncthreads();

    if (t < 64) {
        float s = b3[t];
#pragma unroll 8
        for (int k = 0; k < 128; k++) s += gv[k] * W3[k * 64 + t];
        t1[t] = lrelu(s);
    }
    __syncthreads();
    if (t < 64) {
        float s = b4[t];
#pragma unroll 8
        for (int k = 0; k < 64; k++) s += t1[k] * W4[k * 64 + t];
        t2[t] = lrelu(s);
    }
    __syncthreads();
    if (t < 10) {
        float s = b5[t];
#pragma unroll 8
        for (int k = 0; k < 64; k++) s += t2[k] * W5[k * 10 + t];
        out[g * 10 + t] = s;
    }
}

// ---------------- launch ----------------------------------------------------
// Inputs resolved by ELEMENT COUNT (ordering-agnostic). edge_index/batch are
// int32 (JAX x64 disabled downcasts int64 -> int32).
extern "C" void kernel_launch(void* const* d_in, const int* in_sizes, int n_in,
                              void* d_out, int out_size)
{
    const float* x = nullptr;
    const int* ei = nullptr;
    const int* batch = nullptr;
    const float *W1 = nullptr, *b1 = nullptr, *W2 = nullptr, *b2 = nullptr;
    const float *W3 = nullptr, *b3 = nullptr, *W4 = nullptr, *b4 = nullptr;
    const float *W5 = nullptr, *b5 = nullptr;

    for (int i = 0; i < n_in; i++) {
        const void* p = d_in[i];
        switch (in_sizes[i]) {
            case 12800000: x = (const float*)p; break;
            case 3200000:  ei = (const int*)p; break;
            case 100000:   batch = (const int*)p; break;
            case 16384:    if (!W1) W1 = (const float*)p; else W2 = (const float*)p; break;
            case 8192:     W3 = (const float*)p; break;
            case 4096:     W4 = (const float*)p; break;
            case 640:      W5 = (const float*)p; break;
            case 128:      if (!b1) b1 = (const float*)p; else b2 = (const float*)p; break;
            case 64:       if (!b3) b3 = (const float*)p; else b4 = (const float*)p; break;
            case 10:       b5 = (const float*)p; break;
            default: break;
        }
    }
    float* out = (float*)d_out;
    (void)out_size;

    // CSR build (once, reused by both layers)
    zero_prep_kernel<<<(N_NODES + 255) / 256, 256>>>();
    deg_kernel<<<(N_EDGES + 255) / 256, 256>>>(ei);
    scan_kernel<<<1, 1024>>>();
    fill_kernel<<<(N_EDGES + 255) / 256, 256>>>(ei);

    // layer 1
    gemm_kernel<false><<<N_NODES / 32, 256>>>(x, W1, nullptr);
    agg_kernel<<<(N_NODES * 32 + 255) / 256, 256>>>();

    // layer 2
    gemm_kernel<true><<<N_NODES / 32, 256>>>(nullptr, W2, b1);
    agg_kernel<<<(N_NODES * 32 + 255) / 256, 256>>>();

    // pool + head
    pool_kernel<<<(N_NODES * 32 + 255) / 256, 256>>>(batch, b2);
    head_kernel<<<NG, 128>>>(W3, b3, W4, b4, W5, b5, out);
}